// round 15
// baseline (speedup 1.0000x reference)
#include <cuda_runtime.h>
#include <cuda_fp16.h>
#include <math.h>
#include <stdint.h>

// Problem constants
#define BB 4
#define TT 1024
#define VV 32000
#define DD 1024
#define LL 8
#define HH 16
#define NROWS 4096
#define FFD 4096
#define QKVD 3072

// ---------------- scratch (device globals: allocation-free rule) ----------
__device__ float  g_x[NROWS * DD];                 // residual stream (fp32)
__device__ __half g_h[NROWS * DD];
__device__ __half g_qkv[(size_t)NROWS * QKVD];     // fused q|k|v
__device__ __half g_att[NROWS * DD];
__device__ __half g_ff[NROWS * FFD];
__device__ __half g_wqkv[(size_t)LL * DD * QKVD];  // [K=1024][N=3072] per layer
__device__ float  g_bqkv[LL * QKVD];
__device__ __half g_wo[LL * DD * DD];              // [K][N] row-major fp16
__device__ __half g_w1[(size_t)LL * DD * FFD];
__device__ __half g_w2[(size_t)LL * FFD * DD];
__device__ __half g_head[(size_t)DD * VV];

// ---------------- PTX helpers ---------------------------------------------
__device__ __forceinline__ uint32_t smem_u32(const void* p) {
    uint32_t a;
    asm("{ .reg .u64 t; cvta.to.shared.u64 t, %1; cvt.u32.u64 %0, t; }"
        : "=r"(a) : "l"(p));
    return a;
}
__device__ __forceinline__ void cp16(uint32_t s, const void* g) {
    asm volatile("cp.async.cg.shared.global [%0], [%1], 16;" :: "r"(s), "l"(g));
}
#define CP_COMMIT() asm volatile("cp.async.commit_group;" ::: "memory")
#define CP_WAIT(n) asm volatile("cp.async.wait_group %0;" :: "n"(n) : "memory")

__device__ __forceinline__ void mma_f16(float* c, const uint32_t* a,
                                        const uint32_t* b) {
    asm volatile(
        "mma.sync.aligned.m16n8k16.row.col.f32.f16.f16.f32 "
        "{%0,%1,%2,%3}, {%4,%5,%6,%7}, {%8,%9}, {%0,%1,%2,%3};"
        : "+f"(c[0]), "+f"(c[1]), "+f"(c[2]), "+f"(c[3])
        : "r"(a[0]), "r"(a[1]), "r"(a[2]), "r"(a[3]), "r"(b[0]), "r"(b[1]));
}
__device__ __forceinline__ void ldsm4(uint32_t* r, uint32_t addr) {
    asm volatile("ldmatrix.sync.aligned.m8n8.x4.shared.b16 {%0,%1,%2,%3}, [%4];"
        : "=r"(r[0]), "=r"(r[1]), "=r"(r[2]), "=r"(r[3]) : "r"(addr));
}
__device__ __forceinline__ void ldsm4t(uint32_t* r, uint32_t addr) {
    asm volatile("ldmatrix.sync.aligned.m8n8.x4.trans.shared.b16 {%0,%1,%2,%3}, [%4];"
        : "=r"(r[0]), "=r"(r[1]), "=r"(r[2]), "=r"(r[3]) : "r"(addr));
}
__device__ __forceinline__ void st_half4(__half* p, float4 v) {
    __half2 a = __floats2half2_rn(v.x, v.y);
    __half2 b = __floats2half2_rn(v.z, v.w);
    uint2 u;
    u.x = *(uint32_t*)&a; u.y = *(uint32_t*)&b;
    *(uint2*)p = u;
}

// ---------------- fused weight prep (cast + qkv/bias merge) ----------------
__global__ void prep_kernel(const float* __restrict__ Wq, const float* __restrict__ Wk,
                            const float* __restrict__ Wv, const float* __restrict__ Wo,
                            const float* __restrict__ W1, const float* __restrict__ W2,
                            const float* __restrict__ Hd,
                            const float* __restrict__ bq, const float* __restrict__ bk,
                            const float* __restrict__ bv,
                            __half* __restrict__ wqkv, __half* __restrict__ wo,
                            __half* __restrict__ w1, __half* __restrict__ w2,
                            __half* __restrict__ hd, float* __restrict__ bqkv)
{
    size_t base = ((size_t)blockIdx.x * 256 + threadIdx.x) * 4;
    switch (blockIdx.y) {
    case 0: {   // merged qkv weight: [l][k][n<3072]
        if (base >= (size_t)LL * DD * QKVD) return;
        size_t n = base % QKVD, lk = base / QKVD;
        const float* s = (n < DD) ? Wq : (n < 2 * DD) ? Wk : Wv;
        size_t nn = n & (DD - 1);
        st_half4(wqkv + base, *(const float4*)(s + lk * DD + nn));
        break; }
    case 1: {
        if (base >= (size_t)LL * DD * DD) return;
        st_half4(wo + base, *(const float4*)(Wo + base));
        break; }
    case 2: {
        if (base >= (size_t)LL * DD * FFD) return;
        st_half4(w1 + base, *(const float4*)(W1 + base));
        break; }
    case 3: {
        if (base >= (size_t)LL * FFD * DD) return;
        st_half4(w2 + base, *(const float4*)(W2 + base));
        break; }
    case 4: {
        if (base >= (size_t)DD * VV) return;
        st_half4(hd + base, *(const float4*)(Hd + base));
        break; }
    default: {  // merged qkv bias (fp32)
        if (base >= (size_t)LL * QKVD) return;
        size_t n = base % QKVD, l = base / QKVD;
        const float* s = (n < DD) ? bq : (n < 2 * DD) ? bk : bv;
        *(float4*)(bqkv + base) = *(const float4*)(s + l * DD + (n & (DD - 1)));
        break; }
    }
}

// ---------------- embedding ------------------------------------------------
__global__ void embed_kernel(const int* __restrict__ idx,
                             const float* __restrict__ tok,
                             const float* __restrict__ pos,
                             float* __restrict__ x)
{
    int row = blockIdx.x;
    int t = row % TT;
    int id = idx[row];
    int tid = threadIdx.x;
    const float4* tp = (const float4*)(tok + (size_t)id * DD);
    const float4* pp = (const float4*)(pos + (size_t)t * DD);
    float4 a = tp[tid], b = pp[tid];
    ((float4*)(x + (size_t)row * DD))[tid] =
        make_float4(a.x + b.x, a.y + b.y, a.z + b.z, a.w + b.w);
}

// ---------------- layernorm: warp-per-row, fp32 in / fp16 out --------------
__global__ void ln_kernel(const float* __restrict__ x,
                          const float* __restrict__ g,
                          const float* __restrict__ b,
                          __half* __restrict__ y)
{
    int lane = threadIdx.x & 31, warp = threadIdx.x >> 5;
    int row = blockIdx.x * 8 + warp;
    const float4* xr = (const float4*)(x + (size_t)row * DD);
    float4 v[8];
    float s = 0.f, sq = 0.f;
#pragma unroll
    for (int i = 0; i < 8; i++) {
        v[i] = xr[i * 32 + lane];
        s  += v[i].x + v[i].y + v[i].z + v[i].w;
        sq += v[i].x * v[i].x + v[i].y * v[i].y + v[i].z * v[i].z + v[i].w * v[i].w;
    }
#pragma unroll
    for (int o = 16; o > 0; o >>= 1) {
        s  += __shfl_xor_sync(0xffffffffu, s, o);
        sq += __shfl_xor_sync(0xffffffffu, sq, o);
    }
    float mean = s * (1.f / DD);
    float var  = sq * (1.f / DD) - mean * mean;
    float inv  = rsqrtf(var + 1e-5f);
    const float4* gr = (const float4*)g;
    const float4* br = (const float4*)b;
    __half* yrow = y + (size_t)row * DD;
#pragma unroll
    for (int i = 0; i < 8; i++) {
        float4 gv = gr[i * 32 + lane], bv = br[i * 32 + lane];
        float4 o;
        o.x = (v[i].x - mean) * inv * gv.x + bv.x;
        o.y = (v[i].y - mean) * inv * gv.y + bv.y;
        o.z = (v[i].z - mean) * inv * gv.z + bv.z;
        o.w = (v[i].w - mean) * inv * gv.w + bv.w;
        st_half4(yrow + (i * 32 + lane) * 4, o);
    }
}

// ---------------- fp16 mma.sync GEMM, persistent tiles ---------------------
// C[M,N] = A[M,K] @ B[K,N]. CTA 128x128 tile, 4 warps (64x64), 2 CTAs/SM.
// Persistent: grid = min(ntiles, 296); each CTA strides over tiles.
#define GF_BIAS    1
#define GF_GELU    2
#define GF_RESID   4
#define GF_OUTHALF 8
#define BM 128
#define BN 128
#define BK 32
#define PADH 40                        // A row pad (halves)
#define PADB 136                       // B row pad (halves)
#define A_STGH (BM * PADH)             // 5120
#define B_STGH (BK * PADB)             // 4352
#define STGH   (A_STGH + B_STGH)       // 9472 halves = 18944 B
#define NST 5
#define SMEM_BYTES (NST * STGH * 2)    // 94720 B
#define PERSIST 296

__global__ void __launch_bounds__(128, 2)
tc_gemm(const __half* __restrict__ A, const __half* __restrict__ B,
        const float* __restrict__ bias, const float* __restrict__ resid,
        void* __restrict__ Cout, int M, int N, int K, int flags)
{
    extern __shared__ __half smh[];
    int tid = threadIdx.x;
    int warp = tid >> 5, lane = tid & 31;
    int grp = lane >> 2, tig = lane & 3;
    int NIT = K / BK;
    int m0 = (warp & 1) * 64, n0 = (warp >> 1) * 64;
    int nx = N / BN;
    int ntiles = (M / BM) * nx;

    uint32_t smb = smem_u32(smh);

    uint32_t a_off = (uint32_t)(((m0 + (lane & 7) + 8 * ((lane >> 3) & 1)) * PADH
                     + 8 * ((lane >> 4) & 1)) * 2);
    uint32_t b_off = (uint32_t)(A_STGH * 2 +
                     (((lane & 7) + 8 * ((lane >> 3) & 1)) * PADB
                     + n0 + 8 * ((lane >> 4) & 1)) * 2);

    for (int tile = blockIdx.x; tile < ntiles; tile += gridDim.x) {
        int row0 = (tile / nx) * BM;
        int col0 = (tile % nx) * BN;

        auto load_tile = [&](int slot, int kt) {
            uint32_t ab = smb + slot * (STGH * 2);
            uint32_t bb = ab + A_STGH * 2;
            int k0 = kt * BK;
#pragma unroll
            for (int i = 0; i < 4; i++) {
                int lin = i * 128 + tid;
                int m = lin >> 2, j = lin & 3;
                cp16(ab + (m * PADH + j * 8) * 2,
                     A + (size_t)(row0 + m) * K + k0 + j * 8);
            }
#pragma unroll
            for (int i = 0; i < 4; i++) {
                int lin = i * 128 + tid;
                int kr = lin >> 4, nc = lin & 15;
                cp16(bb + (kr * PADB + nc * 8) * 2,
                     B + (size_t)(k0 + kr) * N + col0 + nc * 8);
            }
        };

        float acc[4][8][4];
#pragma unroll
        for (int mt = 0; mt < 4; mt++)
#pragma unroll
            for (int nt = 0; nt < 8; nt++)
#pragma unroll
                for (int r = 0; r < 4; r++) acc[mt][nt][r] = 0.f;

        // prologue: prefetch distance 3 (stages 0..2), one commit each
        load_tile(0, 0); CP_COMMIT();
        load_tile(1, 1); CP_COMMIT();
        load_tile(2, 2); CP_COMMIT();

        int slot = 0;
        for (int it = 0; it < NIT; it++) {
            CP_WAIT(1);
            if ((it & 1) == 0) __syncthreads();   // barrier every 2 iters
            if (it + 3 < NIT) {
                int ns = slot + 3; if (ns >= NST) ns -= NST;
                load_tile(ns, it + 3);
            }
            CP_COMMIT();                           // uniform group accounting

            uint32_t stage = smb + slot * (STGH * 2);
#pragma unroll
            for (int kk = 0; kk < 2; kk++) {
                uint32_t af[4][4], bq[4][4];
#pragma unroll
                for (int mt = 0; mt < 4; mt++)
                    ldsm4(af[mt], stage + a_off + (mt * 16 * PADH + kk * 16) * 2);
#pragma unroll
                for (int nt2 = 0; nt2 < 4; nt2++)
                    ldsm4t(bq[nt2], stage + b_off + (kk * 16 * PADB + nt2 * 16) * 2);
#pragma unroll
                for (int mt = 0; mt < 4; mt++)
#pragma unroll
                    for (int nt = 0; nt < 8; nt++)
                        mma_f16(acc[mt][nt], af[mt], &bq[nt >> 1][(nt & 1) * 2]);
            }
            if (++slot >= NST) slot = 0;
        }

        // ---- epilogue (registers + global only; smem free for next tile) --
#pragma unroll
        for (int mt = 0; mt < 4; mt++) {
#pragma unroll
            for (int half = 0; half < 2; half++) {
                int r = row0 + m0 + mt * 16 + grp + half * 8;
                const float* rrow = (flags & GF_RESID) ? resid + (size_t)r * N : nullptr;
#pragma unroll
                for (int nt = 0; nt < 8; nt++) {
                    int c = col0 + n0 + nt * 8 + 2 * tig;
                    float v0 = acc[mt][nt][half * 2 + 0];
                    float v1 = acc[mt][nt][half * 2 + 1];
                    if (flags & GF_BIAS) { v0 += bias[c]; v1 += bias[c + 1]; }
                    if (flags & GF_GELU) {
                        v0 = 0.5f * v0 * (1.f + erff(v0 * 0.70710678118654752f));
                        v1 = 0.5f * v1 * (1.f + erff(v1 * 0.70710678118654752f));
                    }
                    if (flags & GF_RESID) {
                        float2 rv = *(const float2*)(rrow + c);
                        v0 += rv.x; v1 += rv.y;
                    }
                    if (flags & GF_OUTHALF) {
                        *(__half2*)((__half*)Cout + (size_t)r * N + c) =
                            __floats2half2_rn(v0, v1);
                    } else {
                        *(float2*)((float*)Cout + (size_t)r * N + c) =
                            make_float2(v0, v1);
                    }
                }
            }
        }
    }
}

// ---------------- tensor-core flash attention: 128 queries / CTA -----------
#define FA_KV_BYTES 9216               // 64 rows x 72 halves x 2B
#define FA_QS_BYTES 18432              // 128 x 72 x 2
#define FA_SMEM (FA_QS_BYTES + 2 * 2 * FA_KV_BYTES)   // 55296

__global__ void __launch_bounds__(256, 1) fa_kernel(
    const __half* __restrict__ QKV, __half* __restrict__ O)
{
    extern __shared__ char fsm[];
    uint32_t smb = smem_u32(fsm);
    __half* Qs = (__half*)fsm;           // [128][72]

    int tid = threadIdx.x;
    int warp = tid >> 5, lane = tid & 31;
    int grp = lane >> 2, tig = lane & 3;
    int bh = blockIdx.y;
    int b = bh >> 4, h = bh & 15;
    int q0 = blockIdx.x * 128;
    int mrow = warp * 16;

    size_t bq_ = ((size_t)b * TT) * QKVD + (size_t)h * 64;
    size_t bk_ = bq_ + DD;
    size_t bv_ = bq_ + 2 * DD;
    size_t bo_ = ((size_t)b * TT) * DD + (size_t)h * 64;

    const __half2 sc2 = __floats2half2_rn(0.125f, 0.125f);
    for (int i = tid; i < 128 * 8; i += 256) {
        int row = i >> 3, c8 = (i & 7) * 8;
        uint4 u = *(const uint4*)(QKV + bq_ + (size_t)(q0 + row) * QKVD + c8);
        __half2* hp = (__half2*)&u;
#pragma unroll
        for (int j = 0; j < 4; j++) hp[j] = __hmul2(hp[j], sc2);
        *(uint4*)&Qs[row * 72 + c8] = u;
    }

    auto load_kv = [&](int buf, int t) {
        uint32_t kb = smb + FA_QS_BYTES + buf * (2 * FA_KV_BYTES);
        uint32_t vb = kb + FA_KV_BYTES;
        int kt0 = t * 64;
#pragma unroll
        for (int i = 0; i < 2; i++) {
            int c = i * 256 + tid;
            int row = c >> 3, col = (c & 7) * 8;
            cp16(kb + (row * 72 + col) * 2,
                 QKV + bk_ + (size_t)(kt0 + row) * QKVD + col);
            cp16(vb + (row * 72 + col) * 2,
                 QKV + bv_ + (size_t)(kt0 + row) * QKVD + col);
        }
    };

    int ntiles = q0 / 64 + 2;
    load_kv(0, 0); CP_COMMIT();
    __syncthreads();

    uint32_t aq[4][4];
#pragma unroll
    for (int s = 0; s < 4; s++) {
        aq[s][0] = *(const uint32_t*)&Qs[(mrow + grp) * 72 + 16 * s + 2 * tig];
        aq[s][1] = *(const uint32_t*)&Qs[(mrow + grp + 8) * 72 + 16 * s + 2 * tig];
        aq[s][2] = *(const uint32_t*)&Qs[(mrow + grp) * 72 + 16 * s + 2 * tig + 8];
        aq[s][3] = *(const uint32_t*)&Qs[(mrow + grp + 8) * 72 + 16 * s + 2 * tig + 8];
    }

    uint32_t k_off = (uint32_t)(((((lane & 7) + 8 * ((lane >> 4) & 1)) * 72)
                     + 8 * ((lane >> 3) & 1)) * 2);
    uint32_t v_off = (uint32_t)(((((lane & 7) + 8 * ((lane >> 3) & 1)) * 72)
                     + 8 * ((lane >> 4) & 1)) * 2);

    float o[8][4];
#pragma unroll
    for (int d = 0; d < 8; d++)
#pragma unroll
        for (int r = 0; r < 4; r++) o[d][r] = 0.f;
    float m0v = -1e30f, m1v = -1e30f, l0 = 0.f, l1 = 0.f;

    for (int t = 0; t < ntiles; t++) {
        int kt0 = t * 64;
        int buf = t & 1;
        bool pf = (t + 1 < ntiles);
        if (pf) { load_kv(buf ^ 1, t + 1); CP_COMMIT(); CP_WAIT(1); }
        else    { CP_WAIT(0); }
        __syncthreads();

        if (kt0 <= q0 + mrow + 15) {
            uint32_t kb = smb + FA_QS_BYTES + buf * (2 * FA_KV_BYTES);
            uint32_t vb = kb + FA_KV_BYTES;

            float sc[8][4];
#pragma unroll
            for (int j = 0; j < 8; j++)
#pragma unroll
                for (int r = 0; r < 4; r++) sc[j][r] = 0.f;
#pragma unroll
            for (int s = 0; s < 4; s++) {
                uint32_t kq[4][4];
#pragma unroll
                for (int j2 = 0; j2 < 4; j2++)
                    ldsm4(kq[j2], kb + k_off + (j2 * 16 * 72 + s * 16) * 2);
#pragma unroll
                for (int j = 0; j < 8; j++)
                    mma_f16(sc[j], aq[s], &kq[j >> 1][(j & 1) * 2]);
            }

            if (kt0 + 63 > q0 + mrow) {
                int gq0 = q0 + mrow + grp, gq1 = gq0 + 8;
#pragma unroll
                for (int j = 0; j < 8; j++) {
                    int gk = kt0 + 8 * j + 2 * tig;
                    if (gk > gq0)     sc[j][0] = -1e30f;
                    if (gk + 1 > gq0) sc[j][1] = -1e30f;
                    if (gk > gq1)     sc[j][2] = -1e30f;
                    if (gk + 1 > gq1) sc[j][3] = -1e30f;
                }
            }

            float mx0 = -1e30f, mx1 = -1e30f;
#pragma unroll
            for (int j = 0; j < 8; j++) {
                mx0 = fmaxf(mx0, fmaxf(sc[j][0], sc[j][1]));
                mx1 = fmaxf(mx1, fmaxf(sc[j][2], sc[j][3]));
            }
            mx0 = fmaxf(mx0, __shfl_xor_sync(0xffffffffu, mx0, 1));
            mx0 = fmaxf(mx0, __shfl_xor_sync(0xffffffffu, mx0, 2));
            mx1 = fmaxf(mx1, __shfl_xor_sync(0xffffffffu, mx1, 1));
            mx1 = fmaxf(mx1, __shfl_xor_sync(0xffffffffu, mx1, 2));

            float mn0 = fmaxf(m0v, mx0), mn1 = fmaxf(m1v, mx1);
            float cr0 = __expf(m0v - mn0), cr1 = __expf(m1v - mn1);
            m0v = mn0; m1v = mn1;

            uint32_t ap[4][4];
            float rs0 = 0.f, rs1 = 0.f;
#pragma unroll
            for (int j = 0; j < 8; j++) {
                float p0 = __expf(sc[j][0] - mn0);
                float p1 = __expf(sc[j][1] - mn0);
                float p2 = __expf(sc[j][2] - mn1);
                float p3 = __expf(sc[j][3] - mn1);
                rs0 += p0 + p1; rs1 += p2 + p3;
                int s = j >> 1, odd = j & 1;
                __half2 h01 = __floats2half2_rn(p0, p1);
                __half2 h23 = __floats2half2_rn(p2, p3);
                ap[s][odd * 2 + 0] = *(uint32_t*)&h01;
                ap[s][odd * 2 + 1] = *(uint32_t*)&h23;
            }
            rs0 += __shfl_xor_sync(0xffffffffu, rs0, 1);
            rs0 += __shfl_xor_sync(0xffffffffu, rs0, 2);
            rs1 += __shfl_xor_sync(0xffffffffu, rs1, 1);
            rs1 += __shfl_xor_sync(0xffffffffu, rs1, 2);
            l0 = l0 * cr0 + rs0;
            l1 = l1 * cr1 + rs1;

#pragma unroll
            for (int d = 0; d < 8; d++) {
                o[d][0] *= cr0; o[d][1] *= cr0;
                o[d][2] *= cr1; o[d][3] *= cr1;
            }

#pragma unroll
            for (int s = 0; s < 4; s++) {
                uint32_t vq[4][4];
#pragma unroll
                for (int d2 = 0; d2 < 4; d2++)
                    ldsm4t(vq[d2], vb + v_off + (s * 16 * 72 + d2 * 16) * 2);
#pragma unroll
                for (int d = 0; d < 8; d++)
                    mma_f16(o[d], ap[s], &vq[d >> 1][(d & 1) * 2]);
            }
        }
        __syncthreads();
    }

    float i0 = 1.f / l0, i1 = 1.f / l1;
    int r0 = q0 + mrow + grp, r1 = r0 + 8;
#pragma unroll
    for (int d = 0; d < 8; d++) {
        int c = 8 * d + 2 * tig;
        *(__half2*)(O + bo_ + (size_t)r0 * DD + c) =
            __floats2half2_rn(o[d][0] * i0, o[d][1] * i0);
        *(__half2*)(O + bo_ + (size_t)r1 * DD + c) =
            __floats2half2_rn(o[d][2] * i1, o[d][3] * i1);
    }
}

// ---------------- host orchestration ---------------------------------------
static inline int pgrid(int M, int N) {
    int t = (M / BM) * (N / BN);
    return t < PERSIST ? t : PERSIST;
}

extern "C" void kernel_launch(void* const* d_in, const int* in_sizes, int n_in,
                              void* d_out, int out_size)
{
    const int*   idx    = (const int*)  d_in[0];
    const float* tok    = (const float*)d_in[1];
    const float* pos    = (const float*)d_in[2];
    const float* ln1g   = (const float*)d_in[3];
    const float* ln1b   = (const float*)d_in[4];
    const float* Wq     = (const float*)d_in[5];
    const float* bq     = (const float*)d_in[6];
    const float* Wk     = (const float*)d_in[7];
    const float* bk     = (const float*)d_in[8];
    const float* Wv     = (const float*)d_in[9];
    const float* bv     = (const float*)d_in[10];
    const float* Wo     = (const float*)d_in[11];
    const float* bo     = (const float*)d_in[12];
    const float* ln2g   = (const float*)d_in[13];
    const float* ln2b   = (const float*)d_in[14];
    const float* W1     = (const float*)d_in[15];
    const float* b1     = (const float*)d_in[16];
    const float* W2     = (const float*)d_in[17];
    const float* b2     = (const float*)d_in[18];
    const float* lnfg   = (const float*)d_in[19];
    const float* lnfb   = (const float*)d_in[20];
    const float* headW  = (const float*)d_in[21];
    float* out = (float*)d_out;

    float *x, *bqkv;
    __half *h, *qkv, *att, *ff;
    __half *wqkv, *wo, *w1, *w2, *head;
    cudaGetSymbolAddress((void**)&x,    g_x);
    cudaGetSymbolAddress((void**)&h,    g_h);
    cudaGetSymbolAddress((void**)&qkv,  g_qkv);
    cudaGetSymbolAddress((void**)&att,  g_att);
    cudaGetSymbolAddress((void**)&ff,   g_ff);
    cudaGetSymbolAddress((void**)&bqkv, g_bqkv);
    cudaGetSymbolAddress((void**)&wqkv, g_wqkv);
    cudaGetSymbolAddress((void**)&wo,   g_wo);
    cudaGetSymbolAddress((void**)&w1,   g_w1);
    cudaGetSymbolAddress((void**)&w2,   g_w2);
    cudaGetSymbolAddress((void**)&head, g_head);

    cudaFuncSetAttribute(tc_gemm, cudaFuncAttributeMaxDynamicSharedMemorySize,
                         SMEM_BYTES);
    cudaFuncSetAttribute(fa_kernel, cudaFuncAttributeMaxDynamicSharedMemorySize,
                         FA_SMEM);

    prep_kernel<<<dim3(32768, 6), 256>>>(Wq, Wk, Wv, Wo, W1, W2, headW,
                                         bq, bk, bv,
                                         wqkv, wo, w1, w2, head, bqkv);
    embed_kernel<<<NROWS, 256>>>(idx, tok, pos, x);

    int gQKV  = pgrid(NROWS, QKVD);          // 296 (768 tiles)
    int gDxD  = pgrid(NROWS, DD);            // 256
    int gDx4D = pgrid(NROWS, FFD);           // 296 (1024 tiles)
    int gHead = pgrid(NROWS, VV);            // 296 (8000 tiles)
    dim3 gAttn(TT / 128, BB * HH);           // (8, 64)
    size_t DxD = (size_t)DD * DD;

    for (int l = 0; l < LL; l++) {
        const __half* wqkv_l = wqkv + (size_t)l * DD * QKVD;
        const __half* wo_l = wo + (size_t)l * DxD;
        const __half* w1_l = w1 + (size_t)l * DD * FFD;
        const __half* w2_l = w2 + (size_t)l * DD * FFD;

        ln_kernel<<<512, 256>>>(x, ln1g + l * DD, ln1b + l * DD, h);
        tc_gemm<<<gQKV, 128, SMEM_BYTES>>>(h, wqkv_l, bqkv + (size_t)l * QKVD,
                                           nullptr, qkv, NROWS, QKVD, DD,
                                           GF_BIAS | GF_OUTHALF);
        fa_kernel<<<gAttn, 256, FA_SMEM>>>(qkv, att);
        tc_gemm<<<gDxD, 128, SMEM_BYTES>>>(att, wo_l, bo + l * DD, x, x,
                                           NROWS, DD, DD, GF_BIAS | GF_RESID);
        ln_kernel<<<512, 256>>>(x, ln2g + l * DD, ln2b + l * DD, h);
        tc_gemm<<<gDx4D, 128, SMEM_BYTES>>>(h, w1_l, b1 + (size_t)l * FFD,
                                            nullptr, ff, NROWS, FFD, DD,
                                            GF_BIAS | GF_GELU | GF_OUTHALF);
        tc_gemm<<<gDxD, 128, SMEM_BYTES>>>(ff, w2_l, b2 + l * DD, x, x,
                                           NROWS, DD, FFD, GF_BIAS | GF_RESID);
    }

    ln_kernel<<<512, 256>>>(x, lnfg, lnfb, h);
    tc_gemm<<<gHead, 128, SMEM_BYTES>>>(h, head, nullptr, nullptr, out,
                                        NROWS, VV, DD, 0);
}

// round 16
// speedup vs baseline: 1.1210x; 1.1210x over previous
#include <cuda_runtime.h>
#include <cuda_fp16.h>
#include <math.h>
#include <stdint.h>

// Problem constants
#define BB 4
#define TT 1024
#define VV 32000
#define DD 1024
#define LL 8
#define HH 16
#define NROWS 4096
#define FFD 4096
#define QKVD 3072

// ---------------- scratch (device globals: allocation-free rule) ----------
__device__ float  g_x[NROWS * DD];                 // residual stream (fp32)
__device__ __half g_h[NROWS * DD];
__device__ __half g_qkv[(size_t)NROWS * QKVD];     // fused q|k|v
__device__ __half g_att[NROWS * DD];
__device__ __half g_ff[NROWS * FFD];
__device__ __half g_wqkv[(size_t)LL * DD * QKVD];  // [K=1024][N=3072] per layer
__device__ float  g_bqkv[LL * QKVD];
__device__ __half g_wo[LL * DD * DD];              // [K][N] row-major fp16
__device__ __half g_w1[(size_t)LL * DD * FFD];
__device__ __half g_w2[(size_t)LL * FFD * DD];
__device__ __half g_head[(size_t)DD * VV];

// ---------------- PTX helpers ---------------------------------------------
__device__ __forceinline__ uint32_t smem_u32(const void* p) {
    uint32_t a;
    asm("{ .reg .u64 t; cvta.to.shared.u64 t, %1; cvt.u32.u64 %0, t; }"
        : "=r"(a) : "l"(p));
    return a;
}
__device__ __forceinline__ void cp16(uint32_t s, const void* g) {
    asm volatile("cp.async.cg.shared.global [%0], [%1], 16;" :: "r"(s), "l"(g));
}
#define CP_COMMIT() asm volatile("cp.async.commit_group;" ::: "memory")
#define CP_WAIT(n) asm volatile("cp.async.wait_group %0;" :: "n"(n) : "memory")

__device__ __forceinline__ void mma_f16(float* c, const uint32_t* a,
                                        const uint32_t* b) {
    asm volatile(
        "mma.sync.aligned.m16n8k16.row.col.f32.f16.f16.f32 "
        "{%0,%1,%2,%3}, {%4,%5,%6,%7}, {%8,%9}, {%0,%1,%2,%3};"
        : "+f"(c[0]), "+f"(c[1]), "+f"(c[2]), "+f"(c[3])
        : "r"(a[0]), "r"(a[1]), "r"(a[2]), "r"(a[3]), "r"(b[0]), "r"(b[1]));
}
__device__ __forceinline__ void ldsm4(uint32_t* r, uint32_t addr) {
    asm volatile("ldmatrix.sync.aligned.m8n8.x4.shared.b16 {%0,%1,%2,%3}, [%4];"
        : "=r"(r[0]), "=r"(r[1]), "=r"(r[2]), "=r"(r[3]) : "r"(addr));
}
__device__ __forceinline__ void ldsm4t(uint32_t* r, uint32_t addr) {
    asm volatile("ldmatrix.sync.aligned.m8n8.x4.trans.shared.b16 {%0,%1,%2,%3}, [%4];"
        : "=r"(r[0]), "=r"(r[1]), "=r"(r[2]), "=r"(r[3]) : "r"(addr));
}
__device__ __forceinline__ void st_half4(__half* p, float4 v) {
    __half2 a = __floats2half2_rn(v.x, v.y);
    __half2 b = __floats2half2_rn(v.z, v.w);
    uint2 u;
    u.x = *(uint32_t*)&a; u.y = *(uint32_t*)&b;
    *(uint2*)p = u;
}

// ---------------- fused weight prep (cast + qkv/bias merge) ----------------
__global__ void prep_kernel(const float* __restrict__ Wq, const float* __restrict__ Wk,
                            const float* __restrict__ Wv, const float* __restrict__ Wo,
                            const float* __restrict__ W1, const float* __restrict__ W2,
                            const float* __restrict__ Hd,
                            const float* __restrict__ bq, const float* __restrict__ bk,
                            const float* __restrict__ bv,
                            __half* __restrict__ wqkv, __half* __restrict__ wo,
                            __half* __restrict__ w1, __half* __restrict__ w2,
                            __half* __restrict__ hd, float* __restrict__ bqkv)
{
    size_t base = ((size_t)blockIdx.x * 256 + threadIdx.x) * 4;
    switch (blockIdx.y) {
    case 0: {   // merged qkv weight: [l][k][n<3072]
        if (base >= (size_t)LL * DD * QKVD) return;
        size_t n = base % QKVD, lk = base / QKVD;
        const float* s = (n < DD) ? Wq : (n < 2 * DD) ? Wk : Wv;
        size_t nn = n & (DD - 1);
        st_half4(wqkv + base, *(const float4*)(s + lk * DD + nn));
        break; }
    case 1: {
        if (base >= (size_t)LL * DD * DD) return;
        st_half4(wo + base, *(const float4*)(Wo + base));
        break; }
    case 2: {
        if (base >= (size_t)LL * DD * FFD) return;
        st_half4(w1 + base, *(const float4*)(W1 + base));
        break; }
    case 3: {
        if (base >= (size_t)LL * FFD * DD) return;
        st_half4(w2 + base, *(const float4*)(W2 + base));
        break; }
    case 4: {
        if (base >= (size_t)DD * VV) return;
        st_half4(hd + base, *(const float4*)(Hd + base));
        break; }
    default: {  // merged qkv bias (fp32)
        if (base >= (size_t)LL * QKVD) return;
        size_t n = base % QKVD, l = base / QKVD;
        const float* s = (n < DD) ? bq : (n < 2 * DD) ? bk : bv;
        *(float4*)(bqkv + base) = *(const float4*)(s + l * DD + (n & (DD - 1)));
        break; }
    }
}

// ---------------- embedding ------------------------------------------------
__global__ void embed_kernel(const int* __restrict__ idx,
                             const float* __restrict__ tok,
                             const float* __restrict__ pos,
                             float* __restrict__ x)
{
    int row = blockIdx.x;
    int t = row % TT;
    int id = idx[row];
    int tid = threadIdx.x;
    const float4* tp = (const float4*)(tok + (size_t)id * DD);
    const float4* pp = (const float4*)(pos + (size_t)t * DD);
    float4 a = tp[tid], b = pp[tid];
    ((float4*)(x + (size_t)row * DD))[tid] =
        make_float4(a.x + b.x, a.y + b.y, a.z + b.z, a.w + b.w);
}

// ---------------- layernorm: warp-per-row, fp32 in / fp16 out --------------
__global__ void ln_kernel(const float* __restrict__ x,
                          const float* __restrict__ g,
                          const float* __restrict__ b,
                          __half* __restrict__ y)
{
    int lane = threadIdx.x & 31, warp = threadIdx.x >> 5;
    int row = blockIdx.x * 8 + warp;
    const float4* xr = (const float4*)(x + (size_t)row * DD);
    float4 v[8];
    float s = 0.f, sq = 0.f;
#pragma unroll
    for (int i = 0; i < 8; i++) {
        v[i] = xr[i * 32 + lane];
        s  += v[i].x + v[i].y + v[i].z + v[i].w;
        sq += v[i].x * v[i].x + v[i].y * v[i].y + v[i].z * v[i].z + v[i].w * v[i].w;
    }
#pragma unroll
    for (int o = 16; o > 0; o >>= 1) {
        s  += __shfl_xor_sync(0xffffffffu, s, o);
        sq += __shfl_xor_sync(0xffffffffu, sq, o);
    }
    float mean = s * (1.f / DD);
    float var  = sq * (1.f / DD) - mean * mean;
    float inv  = rsqrtf(var + 1e-5f);
    const float4* gr = (const float4*)g;
    const float4* br = (const float4*)b;
    __half* yrow = y + (size_t)row * DD;
#pragma unroll
    for (int i = 0; i < 8; i++) {
        float4 gv = gr[i * 32 + lane], bv = br[i * 32 + lane];
        float4 o;
        o.x = (v[i].x - mean) * inv * gv.x + bv.x;
        o.y = (v[i].y - mean) * inv * gv.y + bv.y;
        o.z = (v[i].z - mean) * inv * gv.z + bv.z;
        o.w = (v[i].w - mean) * inv * gv.w + bv.w;
        st_half4(yrow + (i * 32 + lane) * 4, o);
    }
}

// ---------------- fp16 mma.sync GEMM (R14 + dual-kk frag preload) ----------
// C[M,N] = A[M,K] @ B[K,N]. CTA 128x128, 4 warps (64x64), 2 CTAs/SM.
#define GF_BIAS    1
#define GF_GELU    2
#define GF_RESID   4
#define GF_OUTHALF 8
#define BM 128
#define BN 128
#define BK 32
#define PADH 40                        // A row pad (halves)
#define PADB 136                       // B row pad (halves)
#define A_STGH (BM * PADH)             // 5120
#define B_STGH (BK * PADB)             // 4352
#define STGH   (A_STGH + B_STGH)       // 9472 halves = 18944 B
#define NST 5
#define SMEM_BYTES (NST * STGH * 2)    // 94720 B

__global__ void __launch_bounds__(128, 2)
tc_gemm(const __half* __restrict__ A, const __half* __restrict__ B,
        const float* __restrict__ bias, const float* __restrict__ resid,
        void* __restrict__ Cout, int M, int N, int K, int flags)
{
    extern __shared__ __half smh[];
    int tid = threadIdx.x;
    int warp = tid >> 5, lane = tid & 31;
    int grp = lane >> 2, tig = lane & 3;
    int row0 = blockIdx.y * BM, col0 = blockIdx.x * BN;
    int NIT = K / BK;
    int m0 = (warp & 1) * 64, n0 = (warp >> 1) * 64;

    uint32_t smb = smem_u32(smh);

    auto load_tile = [&](int slot, int kt) {
        uint32_t ab = smb + slot * (STGH * 2);
        uint32_t bb = ab + A_STGH * 2;
        int k0 = kt * BK;
#pragma unroll
        for (int i = 0; i < 4; i++) {
            int lin = i * 128 + tid;
            int m = lin >> 2, j = lin & 3;
            cp16(ab + (m * PADH + j * 8) * 2,
                 A + (size_t)(row0 + m) * K + k0 + j * 8);
        }
#pragma unroll
        for (int i = 0; i < 4; i++) {
            int lin = i * 128 + tid;
            int kr = lin >> 4, nc = lin & 15;
            cp16(bb + (kr * PADB + nc * 8) * 2,
                 B + (size_t)(k0 + kr) * N + col0 + nc * 8);
        }
    };

    float acc[4][8][4];
#pragma unroll
    for (int mt = 0; mt < 4; mt++)
#pragma unroll
        for (int nt = 0; nt < 8; nt++)
#pragma unroll
            for (int r = 0; r < 4; r++) acc[mt][nt][r] = 0.f;

    uint32_t a_off = (uint32_t)(((m0 + (lane & 7) + 8 * ((lane >> 3) & 1)) * PADH
                     + 8 * ((lane >> 4) & 1)) * 2);
    uint32_t b_off = (uint32_t)(A_STGH * 2 +
                     (((lane & 7) + 8 * ((lane >> 3) & 1)) * PADB
                     + n0 + 8 * ((lane >> 4) & 1)) * 2);

    // prologue: prefetch distance 3 (stages 0..2), one commit each
    load_tile(0, 0); CP_COMMIT();
    load_tile(1, 1); CP_COMMIT();
    load_tile(2, 2); CP_COMMIT();

    int slot = 0;
    for (int it = 0; it < NIT; it++) {
        CP_WAIT(1);
        if ((it & 1) == 0) __syncthreads();   // barrier every 2 iterations
        if (it + 3 < NIT) {
            int ns = slot + 3; if (ns >= NST) ns -= NST;
            load_tile(ns, it + 3);
        }
        CP_COMMIT();                           // uniform group accounting

        uint32_t stage = smb + slot * (STGH * 2);
        // preload BOTH kk-steps' fragments, then one 64-MMA burst
        uint32_t af[2][4][4], bq[2][4][4];
#pragma unroll
        for (int kk = 0; kk < 2; kk++) {
#pragma unroll
            for (int mt = 0; mt < 4; mt++)
                ldsm4(af[kk][mt], stage + a_off + (mt * 16 * PADH + kk * 16) * 2);
#pragma unroll
            for (int nt2 = 0; nt2 < 4; nt2++)
                ldsm4t(bq[kk][nt2], stage + b_off + (kk * 16 * PADB + nt2 * 16) * 2);
        }
#pragma unroll
        for (int kk = 0; kk < 2; kk++)
#pragma unroll
            for (int mt = 0; mt < 4; mt++)
#pragma unroll
                for (int nt = 0; nt < 8; nt++)
                    mma_f16(acc[mt][nt], af[kk][mt], &bq[kk][nt >> 1][(nt & 1) * 2]);
        if (++slot >= NST) slot = 0;
    }

    // ---- epilogue ---------------------------------------------------------
#pragma unroll
    for (int mt = 0; mt < 4; mt++) {
#pragma unroll
        for (int half = 0; half < 2; half++) {
            int r = row0 + m0 + mt * 16 + grp + half * 8;
            const float* rrow = (flags & GF_RESID) ? resid + (size_t)r * N : nullptr;
#pragma unroll
            for (int nt = 0; nt < 8; nt++) {
                int c = col0 + n0 + nt * 8 + 2 * tig;
                float v0 = acc[mt][nt][half * 2 + 0];
                float v1 = acc[mt][nt][half * 2 + 1];
                if (flags & GF_BIAS) { v0 += bias[c]; v1 += bias[c + 1]; }
                if (flags & GF_GELU) {
                    v0 = 0.5f * v0 * (1.f + erff(v0 * 0.70710678118654752f));
                    v1 = 0.5f * v1 * (1.f + erff(v1 * 0.70710678118654752f));
                }
                if (flags & GF_RESID) {
                    float2 rv = *(const float2*)(rrow + c);
                    v0 += rv.x; v1 += rv.y;
                }
                if (flags & GF_OUTHALF) {
                    *(__half2*)((__half*)Cout + (size_t)r * N + c) =
                        __floats2half2_rn(v0, v1);
                } else {
                    *(float2*)((float*)Cout + (size_t)r * N + c) =
                        make_float2(v0, v1);
                }
            }
        }
    }
}

// ---------------- tensor-core flash attention: 128 queries / CTA -----------
#define FA_KV_BYTES 9216               // 64 rows x 72 halves x 2B
#define FA_QS_BYTES 18432              // 128 x 72 x 2
#define FA_SMEM (FA_QS_BYTES + 2 * 2 * FA_KV_BYTES)   // 55296

__global__ void __launch_bounds__(256, 1) fa_kernel(
    const __half* __restrict__ QKV, __half* __restrict__ O)
{
    extern __shared__ char fsm[];
    uint32_t smb = smem_u32(fsm);
    __half* Qs = (__half*)fsm;           // [128][72]

    int tid = threadIdx.x;
    int warp = tid >> 5, lane = tid & 31;
    int grp = lane >> 2, tig = lane & 3;
    int bh = blockIdx.y;
    int b = bh >> 4, h = bh & 15;
    int q0 = blockIdx.x * 128;
    int mrow = warp * 16;

    size_t bq_ = ((size_t)b * TT) * QKVD + (size_t)h * 64;
    size_t bk_ = bq_ + DD;
    size_t bv_ = bq_ + 2 * DD;
    size_t bo_ = ((size_t)b * TT) * DD + (size_t)h * 64;

    const __half2 sc2 = __floats2half2_rn(0.125f, 0.125f);
    for (int i = tid; i < 128 * 8; i += 256) {
        int row = i >> 3, c8 = (i & 7) * 8;
        uint4 u = *(const uint4*)(QKV + bq_ + (size_t)(q0 + row) * QKVD + c8);
        __half2* hp = (__half2*)&u;
#pragma unroll
        for (int j = 0; j < 4; j++) hp[j] = __hmul2(hp[j], sc2);
        *(uint4*)&Qs[row * 72 + c8] = u;
    }

    auto load_kv = [&](int buf, int t) {
        uint32_t kb = smb + FA_QS_BYTES + buf * (2 * FA_KV_BYTES);
        uint32_t vb = kb + FA_KV_BYTES;
        int kt0 = t * 64;
#pragma unroll
        for (int i = 0; i < 2; i++) {
            int c = i * 256 + tid;
            int row = c >> 3, col = (c & 7) * 8;
            cp16(kb + (row * 72 + col) * 2,
                 QKV + bk_ + (size_t)(kt0 + row) * QKVD + col);
            cp16(vb + (row * 72 + col) * 2,
                 QKV + bv_ + (size_t)(kt0 + row) * QKVD + col);
        }
    };

    int ntiles = q0 / 64 + 2;
    load_kv(0, 0); CP_COMMIT();
    __syncthreads();

    uint32_t aq[4][4];
#pragma unroll
    for (int s = 0; s < 4; s++) {
        aq[s][0] = *(const uint32_t*)&Qs[(mrow + grp) * 72 + 16 * s + 2 * tig];
        aq[s][1] = *(const uint32_t*)&Qs[(mrow + grp + 8) * 72 + 16 * s + 2 * tig];
        aq[s][2] = *(const uint32_t*)&Qs[(mrow + grp) * 72 + 16 * s + 2 * tig + 8];
        aq[s][3] = *(const uint32_t*)&Qs[(mrow + grp + 8) * 72 + 16 * s + 2 * tig + 8];
    }

    uint32_t k_off = (uint32_t)(((((lane & 7) + 8 * ((lane >> 4) & 1)) * 72)
                     + 8 * ((lane >> 3) & 1)) * 2);
    uint32_t v_off = (uint32_t)(((((lane & 7) + 8 * ((lane >> 3) & 1)) * 72)
                     + 8 * ((lane >> 4) & 1)) * 2);

    float o[8][4];
#pragma unroll
    for (int d = 0; d < 8; d++)
#pragma unroll
        for (int r = 0; r < 4; r++) o[d][r] = 0.f;
    float m0v = -1e30f, m1v = -1e30f, l0 = 0.f, l1 = 0.f;

    for (int t = 0; t < ntiles; t++) {
        int kt0 = t * 64;
        int buf = t & 1;
        bool pf = (t + 1 < ntiles);
        if (pf) { load_kv(buf ^ 1, t + 1); CP_COMMIT(); CP_WAIT(1); }
        else    { CP_WAIT(0); }
        __syncthreads();

        if (kt0 <= q0 + mrow + 15) {
            uint32_t kb = smb + FA_QS_BYTES + buf * (2 * FA_KV_BYTES);
            uint32_t vb = kb + FA_KV_BYTES;

            float sc[8][4];
#pragma unroll
            for (int j = 0; j < 8; j++)
#pragma unroll
                for (int r = 0; r < 4; r++) sc[j][r] = 0.f;
#pragma unroll
            for (int s = 0; s < 4; s++) {
                uint32_t kq[4][4];
#pragma unroll
                for (int j2 = 0; j2 < 4; j2++)
                    ldsm4(kq[j2], kb + k_off + (j2 * 16 * 72 + s * 16) * 2);
#pragma unroll
                for (int j = 0; j < 8; j++)
                    mma_f16(sc[j], aq[s], &kq[j >> 1][(j & 1) * 2]);
            }

            if (kt0 + 63 > q0 + mrow) {
                int gq0 = q0 + mrow + grp, gq1 = gq0 + 8;
#pragma unroll
                for (int j = 0; j < 8; j++) {
                    int gk = kt0 + 8 * j + 2 * tig;
                    if (gk > gq0)     sc[j][0] = -1e30f;
                    if (gk + 1 > gq0) sc[j][1] = -1e30f;
                    if (gk > gq1)     sc[j][2] = -1e30f;
                    if (gk + 1 > gq1) sc[j][3] = -1e30f;
                }
            }

            float mx0 = -1e30f, mx1 = -1e30f;
#pragma unroll
            for (int j = 0; j < 8; j++) {
                mx0 = fmaxf(mx0, fmaxf(sc[j][0], sc[j][1]));
                mx1 = fmaxf(mx1, fmaxf(sc[j][2], sc[j][3]));
            }
            mx0 = fmaxf(mx0, __shfl_xor_sync(0xffffffffu, mx0, 1));
            mx0 = fmaxf(mx0, __shfl_xor_sync(0xffffffffu, mx0, 2));
            mx1 = fmaxf(mx1, __shfl_xor_sync(0xffffffffu, mx1, 1));
            mx1 = fmaxf(mx1, __shfl_xor_sync(0xffffffffu, mx1, 2));

            float mn0 = fmaxf(m0v, mx0), mn1 = fmaxf(m1v, mx1);
            float cr0 = __expf(m0v - mn0), cr1 = __expf(m1v - mn1);
            m0v = mn0; m1v = mn1;

            uint32_t ap[4][4];
            float rs0 = 0.f, rs1 = 0.f;
#pragma unroll
            for (int j = 0; j < 8; j++) {
                float p0 = __expf(sc[j][0] - mn0);
                float p1 = __expf(sc[j][1] - mn0);
                float p2 = __expf(sc[j][2] - mn1);
                float p3 = __expf(sc[j][3] - mn1);
                rs0 += p0 + p1; rs1 += p2 + p3;
                int s = j >> 1, odd = j & 1;
                __half2 h01 = __floats2half2_rn(p0, p1);
                __half2 h23 = __floats2half2_rn(p2, p3);
                ap[s][odd * 2 + 0] = *(uint32_t*)&h01;
                ap[s][odd * 2 + 1] = *(uint32_t*)&h23;
            }
            rs0 += __shfl_xor_sync(0xffffffffu, rs0, 1);
            rs0 += __shfl_xor_sync(0xffffffffu, rs0, 2);
            rs1 += __shfl_xor_sync(0xffffffffu, rs1, 1);
            rs1 += __shfl_xor_sync(0xffffffffu, rs1, 2);
            l0 = l0 * cr0 + rs0;
            l1 = l1 * cr1 + rs1;

#pragma unroll
            for (int d = 0; d < 8; d++) {
                o[d][0] *= cr0; o[d][1] *= cr0;
                o[d][2] *= cr1; o[d][3] *= cr1;
            }

#pragma unroll
            for (int s = 0; s < 4; s++) {
                uint32_t vq[4][4];
#pragma unroll
                for (int d2 = 0; d2 < 4; d2++)
                    ldsm4t(vq[d2], vb + v_off + (s * 16 * 72 + d2 * 16) * 2);
#pragma unroll
                for (int d = 0; d < 8; d++)
                    mma_f16(o[d], ap[s], &vq[d >> 1][(d & 1) * 2]);
            }
        }
        __syncthreads();
    }

    float i0 = 1.f / l0, i1 = 1.f / l1;
    int r0 = q0 + mrow + grp, r1 = r0 + 8;
#pragma unroll
    for (int d = 0; d < 8; d++) {
        int c = 8 * d + 2 * tig;
        *(__half2*)(O + bo_ + (size_t)r0 * DD + c) =
            __floats2half2_rn(o[d][0] * i0, o[d][1] * i0);
        *(__half2*)(O + bo_ + (size_t)r1 * DD + c) =
            __floats2half2_rn(o[d][2] * i1, o[d][3] * i1);
    }
}

// ---------------- host orchestration ---------------------------------------
extern "C" void kernel_launch(void* const* d_in, const int* in_sizes, int n_in,
                              void* d_out, int out_size)
{
    const int*   idx    = (const int*)  d_in[0];
    const float* tok    = (const float*)d_in[1];
    const float* pos    = (const float*)d_in[2];
    const float* ln1g   = (const float*)d_in[3];
    const float* ln1b   = (const float*)d_in[4];
    const float* Wq     = (const float*)d_in[5];
    const float* bq     = (const float*)d_in[6];
    const float* Wk     = (const float*)d_in[7];
    const float* bk     = (const float*)d_in[8];
    const float* Wv     = (const float*)d_in[9];
    const float* bv     = (const float*)d_in[10];
    const float* Wo     = (const float*)d_in[11];
    const float* bo     = (const float*)d_in[12];
    const float* ln2g   = (const float*)d_in[13];
    const float* ln2b   = (const float*)d_in[14];
    const float* W1     = (const float*)d_in[15];
    const float* b1     = (const float*)d_in[16];
    const float* W2     = (const float*)d_in[17];
    const float* b2     = (const float*)d_in[18];
    const float* lnfg   = (const float*)d_in[19];
    const float* lnfb   = (const float*)d_in[20];
    const float* headW  = (const float*)d_in[21];
    float* out = (float*)d_out;

    float *x, *bqkv;
    __half *h, *qkv, *att, *ff;
    __half *wqkv, *wo, *w1, *w2, *head;
    cudaGetSymbolAddress((void**)&x,    g_x);
    cudaGetSymbolAddress((void**)&h,    g_h);
    cudaGetSymbolAddress((void**)&qkv,  g_qkv);
    cudaGetSymbolAddress((void**)&att,  g_att);
    cudaGetSymbolAddress((void**)&ff,   g_ff);
    cudaGetSymbolAddress((void**)&bqkv, g_bqkv);
    cudaGetSymbolAddress((void**)&wqkv, g_wqkv);
    cudaGetSymbolAddress((void**)&wo,   g_wo);
    cudaGetSymbolAddress((void**)&w1,   g_w1);
    cudaGetSymbolAddress((void**)&w2,   g_w2);
    cudaGetSymbolAddress((void**)&head, g_head);

    cudaFuncSetAttribute(tc_gemm, cudaFuncAttributeMaxDynamicSharedMemorySize,
                         SMEM_BYTES);
    cudaFuncSetAttribute(fa_kernel, cudaFuncAttributeMaxDynamicSharedMemorySize,
                         FA_SMEM);

    prep_kernel<<<dim3(32768, 6), 256>>>(Wq, Wk, Wv, Wo, W1, W2, headW,
                                         bq, bk, bv,
                                         wqkv, wo, w1, w2, head, bqkv);
    embed_kernel<<<NROWS, 256>>>(idx, tok, pos, x);

    dim3 gQKV(QKVD / BN, NROWS / BM);        // (24, 32)
    dim3 gDxD(DD / BN, NROWS / BM);          // (8, 32)
    dim3 gDx4D(FFD / BN, NROWS / BM);        // (32, 32)
    dim3 gAttn(TT / 128, BB * HH);           // (8, 64)
    size_t DxD = (size_t)DD * DD;

    for (int l = 0; l < LL; l++) {
        const __half* wqkv_l = wqkv + (size_t)l * DD * QKVD;
        const __half* wo_l = wo + (size_t)l * DxD;
        const __half* w1_l = w1 + (size_t)l * DD * FFD;
        const __half* w2_l = w2 + (size_t)l * DD * FFD;

        ln_kernel<<<512, 256>>>(x, ln1g + l * DD, ln1b + l * DD, h);
        tc_gemm<<<gQKV, 128, SMEM_BYTES>>>(h, wqkv_l, bqkv + (size_t)l * QKVD,
                                           nullptr, qkv, NROWS, QKVD, DD,
                                           GF_BIAS | GF_OUTHALF);
        fa_kernel<<<gAttn, 256, FA_SMEM>>>(qkv, att);
        tc_gemm<<<gDxD, 128, SMEM_BYTES>>>(att, wo_l, bo + l * DD, x, x,
                                           NROWS, DD, DD, GF_BIAS | GF_RESID);
        ln_kernel<<<512, 256>>>(x, ln2g + l * DD, ln2b + l * DD, h);
        tc_gemm<<<gDx4D, 128, SMEM_BYTES>>>(h, w1_l, b1 + (size_t)l * FFD,
                                            nullptr, ff, NROWS, FFD, DD,
                                            GF_BIAS | GF_GELU | GF_OUTHALF);
        tc_gemm<<<gDxD, 128, SMEM_BYTES>>>(ff, w2_l, b2 + l * DD, x, x,
                                           NROWS, DD, FFD, GF_BIAS | GF_RESID);
    }

    ln_kernel<<<512, 256>>>(x, lnfg, lnfb, h);
    dim3 gHead(VV / BN, NROWS / BM);         // (250, 32)
    tc_gemm<<<gHead, 128, SMEM_BYTES>>>(h, head, nullptr, nullptr, out,
                                        NROWS, VV, DD, 0);
}